// round 13
// baseline (speedup 1.0000x reference)
#include <cuda_runtime.h>
#include <cuda_fp16.h>
#include <math.h>
#include <stdint.h>

#define D_MODEL 2048
#define NH      16
#define NKV     4
#define HD      128
#define KV_DIM  512
#define QKVW    3072
#define NB      4
#define SEQ     2048
#define TOKENS  (NB * SEQ)
#define KDIM    2048

// Scratch (device globals — no runtime allocation)
__device__ __half g_qkv  [(size_t)TOKENS * QKVW];
__device__ __half g_attn [(size_t)TOKENS * D_MODEL];
__device__ __half g_xc   [(size_t)TOKENS * D_MODEL];
__device__ __half g_wqkvT[(size_t)QKVW   * D_MODEL];
__device__ __half g_woutT[(size_t)D_MODEL* D_MODEL];

// ---------------------------------------------------------------------------
// Helpers
// ---------------------------------------------------------------------------
__device__ __forceinline__ uint32_t smem_u32(const void* p) {
    uint32_t r;
    asm("{ .reg .u64 t; cvta.to.shared.u64 t, %1; cvt.u32.u64 %0, t; }" : "=r"(r) : "l"(p));
    return r;
}
__device__ __forceinline__ void cp16(uint32_t d, const void* s) {
    asm volatile("cp.async.cg.shared.global [%0], [%1], 16;" :: "r"(d), "l"(s));
}
__device__ __forceinline__ void cp_commit() {
    asm volatile("cp.async.commit_group;" ::: "memory");
}
template<int N> __device__ __forceinline__ void cp_wait() {
    asm volatile("cp.async.wait_group %0;" :: "n"(N) : "memory");
}
__device__ __forceinline__ void bar_named(int id) {
    asm volatile("bar.sync %0, 64;" :: "r"(id) : "memory");
}
__device__ __forceinline__ void ldm_x4(uint32_t* r, uint32_t addr) {
    asm volatile("ldmatrix.sync.aligned.m8n8.x4.shared.b16 {%0,%1,%2,%3}, [%4];"
        : "=r"(r[0]), "=r"(r[1]), "=r"(r[2]), "=r"(r[3]) : "r"(addr));
}
__device__ __forceinline__ void ldm_x4_t(uint32_t* r, uint32_t addr) {
    asm volatile("ldmatrix.sync.aligned.m8n8.x4.trans.shared.b16 {%0,%1,%2,%3}, [%4];"
        : "=r"(r[0]), "=r"(r[1]), "=r"(r[2]), "=r"(r[3]) : "r"(addr));
}
__device__ __forceinline__ void mma_f16(float* c, const uint32_t* a, const uint32_t* b) {
    asm volatile(
        "mma.sync.aligned.m16n8k16.row.col.f32.f16.f16.f32 "
        "{%0,%1,%2,%3}, {%4,%5,%6,%7}, {%8,%9}, {%0,%1,%2,%3};"
        : "+f"(c[0]), "+f"(c[1]), "+f"(c[2]), "+f"(c[3])
        : "r"(a[0]), "r"(a[1]), "r"(a[2]), "r"(a[3]), "r"(b[0]), "r"(b[1]));
}
__device__ __forceinline__ uint32_t pack_h2(float x, float y) {
    __half2 h = __floats2half2_rn(x, y);
    return *(uint32_t*)&h;
}

// ---------------------------------------------------------------------------
// FP16 tensor-core GEMM: C = A @ Bt^T + bias. 128x128 tile, BK=64, 3 stages,
// 4 warps (warp tile 64x64): 8 LDSM per 32 MMA. 110 KB smem -> 2 CTA/SM.
// HALF_OUT=1: __half out + fused RMSNorm on q/k heads (q also folded with
// softmax scale). HALF_OUT=0: float out.
// ---------------------------------------------------------------------------
#define BKG  64
#define GSTG 3
#define LDAH 72
#define ASTG_B (128 * LDAH * 2)
#define STG_B  (2 * ASTG_B)

template<int HALF_OUT>
__global__ __launch_bounds__(128) void gemm_mma(
    const __half* __restrict__ A, const __half* __restrict__ Bt,
    const float* __restrict__ bias, void* __restrict__ Cv,
    int N, int K,
    const float* __restrict__ q_scale, const float* __restrict__ k_scale)
{
    extern __shared__ __align__(16) char sh[];
    float* redf = (float*)sh;

    const int tid  = threadIdx.x;
    const int wid  = tid >> 5, lane = tid & 31;
    const int wm   = wid >> 1, wn = wid & 1;       // 2 x 2 warp grid, 64x64 tiles
    const int gid  = lane >> 2, tig = lane & 3;
    const int m0   = blockIdx.y * 128, n0 = blockIdx.x * 128;
    const int NC   = K / BKG;

    const uint32_t sBase = smem_u32(sh);

    const int a_row = (lane & 7) + ((lane >> 3) & 1) * 8;
    const int a_col = (lane >> 4) * 8;
    const int b_row = (lane & 7) + ((lane >> 4) & 1) * 8;
    const int b_col = ((lane >> 3) & 1) * 8;

    float acc[4][8][4];
    #pragma unroll
    for (int i = 0; i < 4; i++)
        #pragma unroll
        for (int j = 0; j < 8; j++)
            #pragma unroll
            for (int t = 0; t < 4; t++) acc[i][j][t] = 0.f;

    auto issue = [&](int c) {
        const int s = c % GSTG;
        const __half* Ag = A  + (size_t)m0 * K + c * BKG;
        const __half* Bg = Bt + (size_t)n0 * K + c * BKG;
        const uint32_t Ad = sBase + s * STG_B;
        const uint32_t Bd = Ad + ASTG_B;
        #pragma unroll
        for (int it = 0; it < 8; it++) {
            const int blk = tid + it * 128;          // 0..1023
            const int row = blk >> 3, quad = blk & 7;
            cp16(Ad + (row * LDAH + quad * 8) * 2, Ag + (size_t)row * K + quad * 8);
            cp16(Bd + (row * LDAH + quad * 8) * 2, Bg + (size_t)row * K + quad * 8);
        }
        cp_commit();
    };

    issue(0);
    issue(1);

    for (int c = 0; c < NC; c++) {
        if (c + 1 >= NC) cp_wait<0>(); else cp_wait<1>();
        __syncthreads();
        if (c + 2 < NC) issue(c + 2);

        const int s = c % GSTG;
        const uint32_t Abase = sBase + s * STG_B + ((wm * 64 + a_row) * LDAH + a_col) * 2;
        const uint32_t Bbase = sBase + s * STG_B + ASTG_B + ((wn * 64 + b_row) * LDAH + b_col) * 2;

        #pragma unroll
        for (int k = 0; k < 4; k++) {
            uint32_t a[4][4], b[4][4];
            #pragma unroll
            for (int i = 0; i < 4; i++)
                ldm_x4(a[i], Abase + i * 16 * LDAH * 2 + k * 32);
            #pragma unroll
            for (int nt = 0; nt < 4; nt++)
                ldm_x4(b[nt], Bbase + nt * 16 * LDAH * 2 + k * 32);
            #pragma unroll
            for (int i = 0; i < 4; i++) {
                #pragma unroll
                for (int j = 0; j < 8; j++)
                    mma_f16(acc[i][j], a[i], &b[j >> 1][(j & 1) * 2]);
            }
        }
    }

    // Add bias
    #pragma unroll
    for (int j = 0; j < 8; j++) {
        const int col = n0 + wn * 64 + j * 8 + tig * 2;
        const float2 bz = *(const float2*)&bias[col];
        #pragma unroll
        for (int i = 0; i < 4; i++) {
            acc[i][j][0] += bz.x; acc[i][j][1] += bz.y;
            acc[i][j][2] += bz.x; acc[i][j][3] += bz.y;
        }
    }

    if (HALF_OUT) {
        __half* C = (__half*)Cv;
        float rlo[4], rhi[4];
        if (n0 < D_MODEL + KV_DIM) {
            // RMSNorm over 128-col head dim; each row split across wn=0,1
            __syncthreads();   // stage smem dead; reuse as reduction array
            float sslo[4], sshi[4];
            #pragma unroll
            for (int i = 0; i < 4; i++) {
                float lo = 0.f, hi = 0.f;
                #pragma unroll
                for (int j = 0; j < 8; j++) {
                    lo += acc[i][j][0] * acc[i][j][0] + acc[i][j][1] * acc[i][j][1];
                    hi += acc[i][j][2] * acc[i][j][2] + acc[i][j][3] * acc[i][j][3];
                }
                lo += __shfl_xor_sync(0xffffffffu, lo, 1);
                lo += __shfl_xor_sync(0xffffffffu, lo, 2);
                hi += __shfl_xor_sync(0xffffffffu, hi, 1);
                hi += __shfl_xor_sync(0xffffffffu, hi, 2);
                sslo[i] = lo; sshi[i] = hi;
            }
            if (tig == 0) {
                #pragma unroll
                for (int i = 0; i < 4; i++) {
                    redf[(wm * 64 + i * 16 + gid) * 2 + wn]     = sslo[i];
                    redf[(wm * 64 + i * 16 + gid + 8) * 2 + wn] = sshi[i];
                }
            }
            __syncthreads();
            #pragma unroll
            for (int i = 0; i < 4; i++) {
                const int rl = wm * 64 + i * 16 + gid;
                const float s0 = redf[rl * 2] + redf[rl * 2 + 1];
                const float s1 = redf[(rl + 8) * 2] + redf[(rl + 8) * 2 + 1];
                rlo[i] = rsqrtf(s0 * (1.0f / HD) + 1e-6f);
                rhi[i] = rsqrtf(s1 * (1.0f / HD) + 1e-6f);
            }
        } else {
            #pragma unroll
            for (int i = 0; i < 4; i++) { rlo[i] = 1.f; rhi[i] = 1.f; }
        }
        const float* sc = (n0 < D_MODEL) ? q_scale : k_scale;
        const float fold = (n0 < D_MODEL) ? 0.08838834764831843f : 1.f;
        #pragma unroll
        for (int j = 0; j < 8; j++) {
            const int si = wn * 64 + j * 8 + tig * 2;
            const float sc0 = ((n0 < D_MODEL + KV_DIM) ? sc[si]     : 1.f) * fold;
            const float sc1 = ((n0 < D_MODEL + KV_DIM) ? sc[si + 1] : 1.f) * fold;
            const int col = n0 + si;
            #pragma unroll
            for (int i = 0; i < 4; i++) {
                const int r0 = m0 + wm * 64 + i * 16 + gid;
                *(uint32_t*)&C[(size_t)r0 * N + col] =
                    pack_h2(acc[i][j][0] * rlo[i] * sc0, acc[i][j][1] * rlo[i] * sc1);
                *(uint32_t*)&C[(size_t)(r0 + 8) * N + col] =
                    pack_h2(acc[i][j][2] * rhi[i] * sc0, acc[i][j][3] * rhi[i] * sc1);
            }
        }
    } else {
        float* C = (float*)Cv;
        #pragma unroll
        for (int j = 0; j < 8; j++) {
            const int col = n0 + wn * 64 + j * 8 + tig * 2;
            #pragma unroll
            for (int i = 0; i < 4; i++) {
                const int r0 = m0 + wm * 64 + i * 16 + gid;
                *(float2*)&C[(size_t)r0 * N + col]       = make_float2(acc[i][j][0], acc[i][j][1]);
                *(float2*)&C[(size_t)(r0 + 8) * N + col] = make_float2(acc[i][j][2], acc[i][j][3]);
            }
        }
    }
}

// ---------------------------------------------------------------------------
// Prep: fp16 conversion of x + weight transpose to fp16
// ---------------------------------------------------------------------------
__global__ __launch_bounds__(256) void cvt_x_f16(const float* __restrict__ in,
                                                 __half* __restrict__ out, int n4)
{
    int i = blockIdx.x * 256 + threadIdx.x;
    if (i >= n4) return;
    float4 v = ((const float4*)in)[i];
    uint2 o;
    o.x = pack_h2(v.x, v.y);
    o.y = pack_h2(v.z, v.w);
    ((uint2*)out)[i] = o;
}

__global__ __launch_bounds__(256) void transpose_f16(const float* __restrict__ W,
                                                     __half* __restrict__ Wt, int K, int N)
{
    __shared__ float t[32][33];
    const int nb = blockIdx.x * 32, kb = blockIdx.y * 32;
    const int x = threadIdx.x & 31, y4 = (threadIdx.x >> 5) * 4;
    #pragma unroll
    for (int i = 0; i < 4; i++) t[y4 + i][x] = W[(size_t)(kb + y4 + i) * N + nb + x];
    __syncthreads();
    #pragma unroll
    for (int i = 0; i < 4; i++)
        Wt[(size_t)(nb + y4 + i) * K + kb + x] = __float2half_rn(t[x][y4 + i]);
}

// ---------------------------------------------------------------------------
// FP16 tensor-core causal flash attention — unchanged from R12.
// ---------------------------------------------------------------------------
#define QS_H 136
#define KS_H 136
#define PS_H 72
#define KVB_B (64 * KS_H * 2)
#define FA_NT 512
#define FA_SMEM ((128*QS_H + 4*64*KS_H + 128*PS_H) * 2 + 512 * 4)

__global__ __launch_bounds__(FA_NT) void flash_attn_tc(
    const __half* __restrict__ qkv, __half* __restrict__ out)
{
    extern __shared__ __align__(16) char smc[];
    __half* Qs = (__half*)smc;
    __half* K0 = Qs + 128 * QS_H;
    __half* V0 = K0 + 2 * 64 * KS_H;
    __half* Ps = V0 + 2 * 64 * KS_H;
    float*  red = (float*)(Ps + 128 * PS_H);

    const int qb = gridDim.x - 1 - blockIdx.x;
    const int h = blockIdx.y, n = blockIdx.z;
    const int kvh = h >> 2;
    const int q0 = qb * 128;
    const int tid = threadIdx.x, wid = tid >> 5, lane = tid & 31;
    const int gid = lane >> 2, tig = lane & 3;
    const int mw = wid & 7;
    const int nh = wid >> 3;
    const int bar_id = mw + 1;

    const __half* base = qkv + (size_t)n * SEQ * QKVW;
    const int qcol = h * HD;
    const int kcol = D_MODEL + kvh * HD;
    const int vcol = D_MODEL + KV_DIM + kvh * HD;

    const uint32_t sQ = smem_u32(Qs), sK0 = smem_u32(K0);
    const uint32_t sV0 = smem_u32(V0), sP = smem_u32(Ps);

    const int ntiles = qb * 2 + 2;

    auto loadKV = [&](int t) {
        const int k0 = t * 64;
        const uint32_t off = (uint32_t)(t & 1) * KVB_B;
        #pragma unroll
        for (int it = 0; it < 2; it++) {
            const int i = (tid + it * FA_NT) * 8;
            const int r = i >> 7, c = i & 127;
            const size_t ro = (size_t)(k0 + r) * QKVW;
            cp16(sK0 + off + (r * KS_H + c) * 2, &base[ro + kcol + c]);
            cp16(sV0 + off + (r * KS_H + c) * 2, &base[ro + vcol + c]);
        }
        cp_commit();
    };

    loadKV(0);

    for (int i = tid * 8; i < 128 * HD; i += FA_NT * 8) {
        const int r = i >> 7, c = i & 127;
        *(uint4*)&Qs[r * QS_H + c] =
            *(const uint4*)&base[(size_t)(q0 + r) * QKVW + qcol + c];
    }

    const int a_row = (lane & 7) + ((lane >> 3) & 1) * 8;
    const int a_col = (lane >> 4) * 8;
    const int b_row = (lane & 7) + ((lane >> 4) & 1) * 8;
    const int b_col = ((lane >> 3) & 1) * 8;
    const int vt_row = (lane & 7) + ((lane >> 3) & 1) * 8;
    const int vt_col = (lane >> 4) * 8;

    const uint32_t QA = sQ + ((mw * 16 + a_row) * QS_H + a_col) * 2;
    const uint32_t KB = sK0 + ((nh * 32 + b_row) * KS_H + b_col) * 2;
    const uint32_t PA = sP + ((mw * 16 + a_row) * PS_H + a_col) * 2;
    const uint32_t VB = sV0 + (vt_row * KS_H + nh * 64 + vt_col) * 2;

    float oacc[8][4];
    #pragma unroll
    for (int j = 0; j < 8; j++)
        #pragma unroll
        for (int t = 0; t < 4; t++) oacc[j][t] = 0.f;

    float m0 = -1e30f, m1 = -1e30f, l0 = 0.f, l1 = 0.f;
    const int rrow0 = mw * 16 + gid;
    const int rrow1 = rrow0 + 8;
    const int row0 = q0 + rrow0, row1 = q0 + rrow1;

    for (int t = 0; t < ntiles; t++) {
        const int k0 = t * 64;
        const uint32_t boff = (uint32_t)(t & 1) * KVB_B;
        cp_wait<0>();
        __syncthreads();

        if (t + 1 < ntiles) loadKV(t + 1);

        float sacc[4][4];
        #pragma unroll
        for (int j = 0; j < 4; j++)
            #pragma unroll
            for (int tt = 0; tt < 4; tt++) sacc[j][tt] = 0.f;

        #pragma unroll
        for (int k = 0; k < 8; k++) {
            uint32_t a[4], b[2][4];
            ldm_x4(a, QA + k * 32);
            ldm_x4(b[0], KB + boff + k * 32);
            ldm_x4(b[1], KB + boff + 16 * KS_H * 2 + k * 32);
            #pragma unroll
            for (int j = 0; j < 4; j++)
                mma_f16(sacc[j], a, &b[j >> 1][(j & 1) * 2]);
        }

        float rm0 = -1e30f, rm1 = -1e30f;
        if (k0 + 64 > q0) {
            #pragma unroll
            for (int j = 0; j < 4; j++) {
                const int c0 = k0 + nh * 32 + j * 8 + 2 * tig, c1 = c0 + 1;
                sacc[j][0] = (c0 <= row0) ? sacc[j][0] : -1e30f;
                sacc[j][1] = (c1 <= row0) ? sacc[j][1] : -1e30f;
                sacc[j][2] = (c0 <= row1) ? sacc[j][2] : -1e30f;
                sacc[j][3] = (c1 <= row1) ? sacc[j][3] : -1e30f;
                rm0 = fmaxf(rm0, fmaxf(sacc[j][0], sacc[j][1]));
                rm1 = fmaxf(rm1, fmaxf(sacc[j][2], sacc[j][3]));
            }
        } else {
            #pragma unroll
            for (int j = 0; j < 4; j++) {
                rm0 = fmaxf(rm0, fmaxf(sacc[j][0], sacc[j][1]));
                rm1 = fmaxf(rm1, fmaxf(sacc[j][2], sacc[j][3]));
            }
        }
        rm0 = fmaxf(rm0, __shfl_xor_sync(0xffffffffu, rm0, 1));
        rm0 = fmaxf(rm0, __shfl_xor_sync(0xffffffffu, rm0, 2));
        rm1 = fmaxf(rm1, __shfl_xor_sync(0xffffffffu, rm1, 1));
        rm1 = fmaxf(rm1, __shfl_xor_sync(0xffffffffu, rm1, 2));
        if (tig == 0) {
            red[rrow0 * 2 + nh] = rm0;
            red[rrow1 * 2 + nh] = rm1;
        }
        bar_named(bar_id);

        const float mn0 = fmaxf(m0, fmaxf(red[rrow0 * 2], red[rrow0 * 2 + 1]));
        const float mn1 = fmaxf(m1, fmaxf(red[rrow1 * 2], red[rrow1 * 2 + 1]));
        const float cor0 = __expf(m0 - mn0), cor1 = __expf(m1 - mn1);
        m0 = mn0; m1 = mn1;

        float ps0 = 0.f, ps1 = 0.f;
        #pragma unroll
        for (int j = 0; j < 4; j++) {
            const float p00 = __expf(sacc[j][0] - mn0);
            const float p01 = __expf(sacc[j][1] - mn0);
            const float p10 = __expf(sacc[j][2] - mn1);
            const float p11 = __expf(sacc[j][3] - mn1);
            ps0 += p00 + p01; ps1 += p10 + p11;
            const int pc = nh * 32 + j * 8 + 2 * tig;
            *(uint32_t*)&Ps[rrow0 * PS_H + pc] = pack_h2(p00, p01);
            *(uint32_t*)&Ps[rrow1 * PS_H + pc] = pack_h2(p10, p11);
        }
        ps0 += __shfl_xor_sync(0xffffffffu, ps0, 1);
        ps0 += __shfl_xor_sync(0xffffffffu, ps0, 2);
        ps1 += __shfl_xor_sync(0xffffffffu, ps1, 1);
        ps1 += __shfl_xor_sync(0xffffffffu, ps1, 2);
        l0 = l0 * cor0 + ps0;
        l1 = l1 * cor1 + ps1;

        #pragma unroll
        for (int j = 0; j < 8; j++) {
            oacc[j][0] *= cor0; oacc[j][1] *= cor0;
            oacc[j][2] *= cor1; oacc[j][3] *= cor1;
        }

        bar_named(bar_id);

        #pragma unroll
        for (int kk = 0; kk < 4; kk++) {
            uint32_t a[4];
            ldm_x4(a, PA + kk * 32);
            #pragma unroll
            for (int nt = 0; nt < 4; nt++) {
                uint32_t b[4];
                ldm_x4_t(b, VB + boff + kk * 16 * KS_H * 2 + nt * 32);
                mma_f16(oacc[2 * nt],     a, &b[0]);
                mma_f16(oacc[2 * nt + 1], a, &b[2]);
            }
        }
    }

    if (tig == 0) {
        red[256 + rrow0 * 2 + nh] = l0;
        red[256 + rrow1 * 2 + nh] = l1;
    }
    bar_named(bar_id);
    const float i0 = 1.f / (red[256 + rrow0 * 2] + red[256 + rrow0 * 2 + 1]);
    const float i1 = 1.f / (red[256 + rrow1 * 2] + red[256 + rrow1 * 2 + 1]);

    __half* op0 = out + (size_t)(n * SEQ + row0) * D_MODEL + h * HD + nh * 64;
    __half* op1 = out + (size_t)(n * SEQ + row1) * D_MODEL + h * HD + nh * 64;
    #pragma unroll
    for (int j = 0; j < 8; j++) {
        const int c = j * 8 + 2 * tig;
        *(uint32_t*)&op0[c] = pack_h2(oacc[j][0] * i0, oacc[j][1] * i0);
        *(uint32_t*)&op1[c] = pack_h2(oacc[j][2] * i1, oacc[j][3] * i1);
    }
}

// ---------------------------------------------------------------------------
extern "C" void kernel_launch(void* const* d_in, const int* in_sizes, int n_in,
                              void* d_out, int out_size)
{
    const float* x       = (const float*)d_in[0];
    const float* Wqkv    = (const float*)d_in[1];
    const float* bqkv    = (const float*)d_in[2];
    const float* q_scale = (const float*)d_in[3];
    const float* k_scale = (const float*)d_in[4];
    const float* Wout    = (const float*)d_in[5];
    const float* bout    = (const float*)d_in[6];
    float* out = (float*)d_out;

    __half *qkv, *attn, *xc, *wqT, *woT;
    cudaGetSymbolAddress((void**)&qkv,  g_qkv);
    cudaGetSymbolAddress((void**)&attn, g_attn);
    cudaGetSymbolAddress((void**)&xc,   g_xc);
    cudaGetSymbolAddress((void**)&wqT,  g_wqkvT);
    cudaGetSymbolAddress((void**)&woT,  g_woutT);

    // Prep: fp16 conversion of x; transpose+convert weights
    cvt_x_f16<<<(TOKENS * D_MODEL / 4 + 255) / 256, 256>>>(x, xc, TOKENS * D_MODEL / 4);
    transpose_f16<<<dim3(QKVW / 32, KDIM / 32), 256>>>(Wqkv, wqT, KDIM, QKVW);
    transpose_f16<<<dim3(D_MODEL / 32, KDIM / 32), 256>>>(Wout, woT, KDIM, D_MODEL);

    const int gsmem = GSTG * STG_B;   // 110,592 B
    cudaFuncSetAttribute(gemm_mma<1>, cudaFuncAttributeMaxDynamicSharedMemorySize, gsmem);
    cudaFuncSetAttribute(gemm_mma<0>, cudaFuncAttributeMaxDynamicSharedMemorySize, gsmem);

    // 1) QKV projection + fused RMSNorm (q heads pre-scaled by 1/sqrt(HD))
    gemm_mma<1><<<dim3(QKVW / 128, TOKENS / 128), 128, gsmem>>>(
        xc, wqT, bqkv, qkv, QKVW, KDIM, q_scale, k_scale);

    // 2) FP16 tensor-core causal flash attention
    cudaFuncSetAttribute(flash_attn_tc, cudaFuncAttributeMaxDynamicSharedMemorySize, FA_SMEM);
    flash_attn_tc<<<dim3(SEQ / 128, NH, NB), FA_NT, FA_SMEM>>>(qkv, attn);

    // 3) Output projection (fp32 out)
    gemm_mma<0><<<dim3(D_MODEL / 128, TOKENS / 128), 128, gsmem>>>(
        attn, woT, bout, out, D_MODEL, KDIM, nullptr, nullptr);
}

// round 14
// speedup vs baseline: 1.0835x; 1.0835x over previous
#include <cuda_runtime.h>
#include <cuda_fp16.h>
#include <math.h>
#include <stdint.h>

#define D_MODEL 2048
#define NH      16
#define NKV     4
#define HD      128
#define KV_DIM  512
#define QKVW    3072
#define NB      4
#define SEQ     2048
#define TOKENS  (NB * SEQ)
#define KDIM    2048

// Scratch (device globals — no runtime allocation)
__device__ __half g_qkv  [(size_t)TOKENS * QKVW];
__device__ __half g_attn [(size_t)TOKENS * D_MODEL];
__device__ __half g_xc   [(size_t)TOKENS * D_MODEL];
__device__ __half g_wqkvT[(size_t)QKVW   * D_MODEL];
__device__ __half g_woutT[(size_t)D_MODEL* D_MODEL];

// ---------------------------------------------------------------------------
// Helpers
// ---------------------------------------------------------------------------
__device__ __forceinline__ uint32_t smem_u32(const void* p) {
    uint32_t r;
    asm("{ .reg .u64 t; cvta.to.shared.u64 t, %1; cvt.u32.u64 %0, t; }" : "=r"(r) : "l"(p));
    return r;
}
__device__ __forceinline__ void cp16(uint32_t d, const void* s) {
    asm volatile("cp.async.cg.shared.global [%0], [%1], 16;" :: "r"(d), "l"(s));
}
__device__ __forceinline__ void cp_commit() {
    asm volatile("cp.async.commit_group;" ::: "memory");
}
template<int N> __device__ __forceinline__ void cp_wait() {
    asm volatile("cp.async.wait_group %0;" :: "n"(N) : "memory");
}
__device__ __forceinline__ void ldm_x4(uint32_t* r, uint32_t addr) {
    asm volatile("ldmatrix.sync.aligned.m8n8.x4.shared.b16 {%0,%1,%2,%3}, [%4];"
        : "=r"(r[0]), "=r"(r[1]), "=r"(r[2]), "=r"(r[3]) : "r"(addr));
}
__device__ __forceinline__ void ldm_x4_t(uint32_t* r, uint32_t addr) {
    asm volatile("ldmatrix.sync.aligned.m8n8.x4.trans.shared.b16 {%0,%1,%2,%3}, [%4];"
        : "=r"(r[0]), "=r"(r[1]), "=r"(r[2]), "=r"(r[3]) : "r"(addr));
}
__device__ __forceinline__ void mma_f16(float* c, const uint32_t* a, const uint32_t* b) {
    asm volatile(
        "mma.sync.aligned.m16n8k16.row.col.f32.f16.f16.f32 "
        "{%0,%1,%2,%3}, {%4,%5,%6,%7}, {%8,%9}, {%0,%1,%2,%3};"
        : "+f"(c[0]), "+f"(c[1]), "+f"(c[2]), "+f"(c[3])
        : "r"(a[0]), "r"(a[1]), "r"(a[2]), "r"(a[3]), "r"(b[0]), "r"(b[1]));
}
__device__ __forceinline__ uint32_t pack_h2(float x, float y) {
    __half2 h = __floats2half2_rn(x, y);
    return *(uint32_t*)&h;
}

// ---------------------------------------------------------------------------
// FP16 tensor-core GEMM (R12 config: 256 thr, 8 warps, 64x32 warp tile,
// 128x128 CTA tile, BK=64, 3 stages, 110 KB -> 2 CTA/SM).
// HALF_OUT=1: __half out + fused RMSNorm on q/k heads (q folded w/ softmax
// scale). HALF_OUT=0: float out.
// ---------------------------------------------------------------------------
#define BKG  64
#define GSTG 3
#define LDAH 72
#define ASTG_B (128 * LDAH * 2)
#define STG_B  (2 * ASTG_B)

template<int HALF_OUT>
__global__ __launch_bounds__(256) void gemm_mma(
    const __half* __restrict__ A, const __half* __restrict__ Bt,
    const float* __restrict__ bias, void* __restrict__ Cv,
    int N, int K,
    const float* __restrict__ q_scale, const float* __restrict__ k_scale)
{
    extern __shared__ __align__(16) char sh[];
    float* redf = (float*)sh;

    const int tid  = threadIdx.x;
    const int wid  = tid >> 5, lane = tid & 31;
    const int wm   = wid >> 2, wn = wid & 3;
    const int gid  = lane >> 2, tig = lane & 3;
    const int m0   = blockIdx.y * 128, n0 = blockIdx.x * 128;
    const int NC   = K / BKG;

    const uint32_t sBase = smem_u32(sh);

    const int a_row = (lane & 7) + ((lane >> 3) & 1) * 8;
    const int a_col = (lane >> 4) * 8;
    const int b_row = (lane & 7) + ((lane >> 4) & 1) * 8;
    const int b_col = ((lane >> 3) & 1) * 8;

    float acc[4][4][4];
    #pragma unroll
    for (int i = 0; i < 4; i++)
        #pragma unroll
        for (int j = 0; j < 4; j++)
            #pragma unroll
            for (int t = 0; t < 4; t++) acc[i][j][t] = 0.f;

    auto issue = [&](int c) {
        const int s = c % GSTG;
        const __half* Ag = A  + (size_t)m0 * K + c * BKG;
        const __half* Bg = Bt + (size_t)n0 * K + c * BKG;
        const uint32_t Ad = sBase + s * STG_B;
        const uint32_t Bd = Ad + ASTG_B;
        #pragma unroll
        for (int it = 0; it < 4; it++) {
            const int blk = tid + it * 256;
            const int row = blk >> 3, quad = blk & 7;
            cp16(Ad + (row * LDAH + quad * 8) * 2, Ag + (size_t)row * K + quad * 8);
            cp16(Bd + (row * LDAH + quad * 8) * 2, Bg + (size_t)row * K + quad * 8);
        }
        cp_commit();
    };

    issue(0);
    issue(1);

    for (int c = 0; c < NC; c++) {
        if (c + 1 >= NC) cp_wait<0>(); else cp_wait<1>();
        __syncthreads();
        if (c + 2 < NC) issue(c + 2);

        const int s = c % GSTG;
        const uint32_t Abase = sBase + s * STG_B + ((wm * 64 + a_row) * LDAH + a_col) * 2;
        const uint32_t Bbase = sBase + s * STG_B + ASTG_B + ((wn * 32 + b_row) * LDAH + b_col) * 2;

        #pragma unroll
        for (int k = 0; k < 4; k++) {
            uint32_t a[4][4], b[2][4];
            #pragma unroll
            for (int i = 0; i < 4; i++)
                ldm_x4(a[i], Abase + i * 16 * LDAH * 2 + k * 32);
            #pragma unroll
            for (int j2 = 0; j2 < 2; j2++)
                ldm_x4(b[j2], Bbase + j2 * 16 * LDAH * 2 + k * 32);
            #pragma unroll
            for (int i = 0; i < 4; i++) {
                #pragma unroll
                for (int j = 0; j < 4; j++)
                    mma_f16(acc[i][j], a[i], &b[j >> 1][(j & 1) * 2]);
            }
        }
    }

    #pragma unroll
    for (int j = 0; j < 4; j++) {
        const int col = n0 + wn * 32 + j * 8 + tig * 2;
        const float2 bz = *(const float2*)&bias[col];
        #pragma unroll
        for (int i = 0; i < 4; i++) {
            acc[i][j][0] += bz.x; acc[i][j][1] += bz.y;
            acc[i][j][2] += bz.x; acc[i][j][3] += bz.y;
        }
    }

    if (HALF_OUT) {
        __half* C = (__half*)Cv;
        float rlo[4], rhi[4];
        if (n0 < D_MODEL + KV_DIM) {
            __syncthreads();
            float sslo[4], sshi[4];
            #pragma unroll
            for (int i = 0; i < 4; i++) {
                float lo = 0.f, hi = 0.f;
                #pragma unroll
                for (int j = 0; j < 4; j++) {
                    lo += acc[i][j][0] * acc[i][j][0] + acc[i][j][1] * acc[i][j][1];
                    hi += acc[i][j][2] * acc[i][j][2] + acc[i][j][3] * acc[i][j][3];
                }
                lo += __shfl_xor_sync(0xffffffffu, lo, 1);
                lo += __shfl_xor_sync(0xffffffffu, lo, 2);
                hi += __shfl_xor_sync(0xffffffffu, hi, 1);
                hi += __shfl_xor_sync(0xffffffffu, hi, 2);
                sslo[i] = lo; sshi[i] = hi;
            }
            if (tig == 0) {
                #pragma unroll
                for (int i = 0; i < 4; i++) {
                    redf[(wm * 64 + i * 16 + gid) * 4 + wn]     = sslo[i];
                    redf[(wm * 64 + i * 16 + gid + 8) * 4 + wn] = sshi[i];
                }
            }
            __syncthreads();
            #pragma unroll
            for (int i = 0; i < 4; i++) {
                const int rl = wm * 64 + i * 16 + gid;
                const float s0 = redf[rl * 4] + redf[rl * 4 + 1] + redf[rl * 4 + 2] + redf[rl * 4 + 3];
                const float s1 = redf[(rl + 8) * 4] + redf[(rl + 8) * 4 + 1] + redf[(rl + 8) * 4 + 2] + redf[(rl + 8) * 4 + 3];
                rlo[i] = rsqrtf(s0 * (1.0f / HD) + 1e-6f);
                rhi[i] = rsqrtf(s1 * (1.0f / HD) + 1e-6f);
            }
        } else {
            #pragma unroll
            for (int i = 0; i < 4; i++) { rlo[i] = 1.f; rhi[i] = 1.f; }
        }
        const float* sc = (n0 < D_MODEL) ? q_scale : k_scale;
        const float fold = (n0 < D_MODEL) ? 0.08838834764831843f : 1.f;
        #pragma unroll
        for (int j = 0; j < 4; j++) {
            const int si = wn * 32 + j * 8 + tig * 2;
            const float sc0 = ((n0 < D_MODEL + KV_DIM) ? sc[si]     : 1.f) * fold;
            const float sc1 = ((n0 < D_MODEL + KV_DIM) ? sc[si + 1] : 1.f) * fold;
            const int col = n0 + si;
            #pragma unroll
            for (int i = 0; i < 4; i++) {
                const int r0 = m0 + wm * 64 + i * 16 + gid;
                *(uint32_t*)&C[(size_t)r0 * N + col] =
                    pack_h2(acc[i][j][0] * rlo[i] * sc0, acc[i][j][1] * rlo[i] * sc1);
                *(uint32_t*)&C[(size_t)(r0 + 8) * N + col] =
                    pack_h2(acc[i][j][2] * rhi[i] * sc0, acc[i][j][3] * rhi[i] * sc1);
            }
        }
    } else {
        float* C = (float*)Cv;
        #pragma unroll
        for (int j = 0; j < 4; j++) {
            const int col = n0 + wn * 32 + j * 8 + tig * 2;
            #pragma unroll
            for (int i = 0; i < 4; i++) {
                const int r0 = m0 + wm * 64 + i * 16 + gid;
                *(float2*)&C[(size_t)r0 * N + col]       = make_float2(acc[i][j][0], acc[i][j][1]);
                *(float2*)&C[(size_t)(r0 + 8) * N + col] = make_float2(acc[i][j][2], acc[i][j][3]);
            }
        }
    }
}

// ---------------------------------------------------------------------------
// Prep: fp16 conversion of x + weight transpose to fp16
// ---------------------------------------------------------------------------
__global__ __launch_bounds__(256) void cvt_x_f16(const float* __restrict__ in,
                                                 __half* __restrict__ out, int n4)
{
    int i = blockIdx.x * 256 + threadIdx.x;
    if (i >= n4) return;
    float4 v = ((const float4*)in)[i];
    uint2 o;
    o.x = pack_h2(v.x, v.y);
    o.y = pack_h2(v.z, v.w);
    ((uint2*)out)[i] = o;
}

__global__ __launch_bounds__(256) void transpose_f16(const float* __restrict__ W,
                                                     __half* __restrict__ Wt, int K, int N)
{
    __shared__ float t[32][33];
    const int nb = blockIdx.x * 32, kb = blockIdx.y * 32;
    const int x = threadIdx.x & 31, y4 = (threadIdx.x >> 5) * 4;
    #pragma unroll
    for (int i = 0; i < 4; i++) t[y4 + i][x] = W[(size_t)(kb + y4 + i) * N + nb + x];
    __syncthreads();
    #pragma unroll
    for (int i = 0; i < 4; i++)
        Wt[(size_t)(nb + y4 + i) * K + kb + x] = __float2half_rn(t[x][y4 + i]);
}

// ---------------------------------------------------------------------------
// FP16 tensor-core causal flash attention — 256 thr / 8 warps, warp owns a
// full 16-row band. P stays in registers (S C-frag == PV A-frag layout).
// Softmax fully warp-local; ONE __syncthreads per tile (KV ring rotation).
// Double-buffered K/V; V^T via ldmatrix.trans.
// ---------------------------------------------------------------------------
#define QS_H 136
#define KS_H 136
#define KVB_B (64 * KS_H * 2)
#define FA_NT 256
#define FA_SMEM ((128*QS_H + 4*64*KS_H) * 2)

__global__ __launch_bounds__(FA_NT) void flash_attn_tc(
    const __half* __restrict__ qkv, __half* __restrict__ out)
{
    extern __shared__ __align__(16) char smc[];
    __half* Qs = (__half*)smc;                 // [128][136]
    __half* K0 = Qs + 128 * QS_H;              // [2][64][136]
    __half* V0 = K0 + 2 * 64 * KS_H;           // [2][64][136]

    const int qb = gridDim.x - 1 - blockIdx.x;
    const int h = blockIdx.y, n = blockIdx.z;
    const int kvh = h >> 2;
    const int q0 = qb * 128;
    const int tid = threadIdx.x, wid = tid >> 5, lane = tid & 31;
    const int gid = lane >> 2, tig = lane & 3;

    const __half* base = qkv + (size_t)n * SEQ * QKVW;
    const int qcol = h * HD;
    const int kcol = D_MODEL + kvh * HD;
    const int vcol = D_MODEL + KV_DIM + kvh * HD;

    const uint32_t sQ = smem_u32(Qs), sK0 = smem_u32(K0);
    const uint32_t sV0 = smem_u32(V0);

    const int ntiles = qb * 2 + 2;

    auto loadKV = [&](int t) {
        const int k0 = t * 64;
        const uint32_t off = (uint32_t)(t & 1) * KVB_B;
        #pragma unroll
        for (int it = 0; it < 4; it++) {
            const int i = (tid + it * FA_NT) * 8;    // halves
            const int r = i >> 7, c = i & 127;
            const size_t ro = (size_t)(k0 + r) * QKVW;
            cp16(sK0 + off + (r * KS_H + c) * 2, &base[ro + kcol + c]);
            cp16(sV0 + off + (r * KS_H + c) * 2, &base[ro + vcol + c]);
        }
        cp_commit();
    };

    loadKV(0);

    for (int i = tid * 8; i < 128 * HD; i += FA_NT * 8) {
        const int r = i >> 7, c = i & 127;
        *(uint4*)&Qs[r * QS_H + c] =
            *(const uint4*)&base[(size_t)(q0 + r) * QKVW + qcol + c];
    }

    const int a_row = (lane & 7) + ((lane >> 3) & 1) * 8;
    const int a_col = (lane >> 4) * 8;
    const int b_row = (lane & 7) + ((lane >> 4) & 1) * 8;
    const int b_col = ((lane >> 3) & 1) * 8;
    const int vt_row = (lane & 7) + ((lane >> 3) & 1) * 8;   // k rows
    const int vt_col = (lane >> 4) * 8;                      // n cols

    const uint32_t QA = sQ + ((wid * 16 + a_row) * QS_H + a_col) * 2;
    const uint32_t KB = sK0 + (b_row * KS_H + b_col) * 2;
    const uint32_t VB = sV0 + (vt_row * KS_H + vt_col) * 2;

    float oacc[16][4];
    #pragma unroll
    for (int j = 0; j < 16; j++)
        #pragma unroll
        for (int t = 0; t < 4; t++) oacc[j][t] = 0.f;

    float m0 = -1e30f, m1 = -1e30f, l0 = 0.f, l1 = 0.f;
    const int row0 = q0 + wid * 16 + gid;
    const int row1 = row0 + 8;

    for (int t = 0; t < ntiles; t++) {
        const int k0 = t * 64;
        const uint32_t boff = (uint32_t)(t & 1) * KVB_B;
        cp_wait<0>();
        __syncthreads();   // KV(t) visible; buffer (t+1)&1 retired (read in t-1)

        if (t + 1 < ntiles) loadKV(t + 1);

        // S = Q @ K^T : warp = 16 rows x 64 cols; 8 n8 tiles x 8 k16 steps
        float sacc[8][4];
        #pragma unroll
        for (int j = 0; j < 8; j++)
            #pragma unroll
            for (int tt = 0; tt < 4; tt++) sacc[j][tt] = 0.f;

        #pragma unroll
        for (int k = 0; k < 8; k++) {
            uint32_t a[4], b[4][4];
            ldm_x4(a, QA + k * 32);
            #pragma unroll
            for (int nt = 0; nt < 4; nt++)
                ldm_x4(b[nt], KB + boff + nt * 16 * KS_H * 2 + k * 32);
            #pragma unroll
            for (int j = 0; j < 8; j++)
                mma_f16(sacc[j], a, &b[j >> 1][(j & 1) * 2]);
        }

        // Causal mask (boundary tiles only) + row max — fully warp-local
        float rm0 = -1e30f, rm1 = -1e30f;
        if (k0 + 64 > q0) {
            #pragma unroll
            for (int j = 0; j < 8; j++) {
                const int c0 = k0 + j * 8 + 2 * tig, c1 = c0 + 1;
                sacc[j][0] = (c0 <= row0) ? sacc[j][0] : -1e30f;
                sacc[j][1] = (c1 <= row0) ? sacc[j][1] : -1e30f;
                sacc[j][2] = (c0 <= row1) ? sacc[j][2] : -1e30f;
                sacc[j][3] = (c1 <= row1) ? sacc[j][3] : -1e30f;
                rm0 = fmaxf(rm0, fmaxf(sacc[j][0], sacc[j][1]));
                rm1 = fmaxf(rm1, fmaxf(sacc[j][2], sacc[j][3]));
            }
        } else {
            #pragma unroll
            for (int j = 0; j < 8; j++) {
                rm0 = fmaxf(rm0, fmaxf(sacc[j][0], sacc[j][1]));
                rm1 = fmaxf(rm1, fmaxf(sacc[j][2], sacc[j][3]));
            }
        }
        rm0 = fmaxf(rm0, __shfl_xor_sync(0xffffffffu, rm0, 1));
        rm0 = fmaxf(rm0, __shfl_xor_sync(0xffffffffu, rm0, 2));
        rm1 = fmaxf(rm1, __shfl_xor_sync(0xffffffffu, rm1, 1));
        rm1 = fmaxf(rm1, __shfl_xor_sync(0xffffffffu, rm1, 2));

        const float mn0 = fmaxf(m0, rm0), mn1 = fmaxf(m1, rm1);
        const float cor0 = __expf(m0 - mn0), cor1 = __expf(m1 - mn1);
        m0 = mn0; m1 = mn1;

        // exp -> fp16 pairs kept in registers (C-frag layout == A-frag layout)
        uint32_t plo[8], phi[8];
        float ps0 = 0.f, ps1 = 0.f;
        #pragma unroll
        for (int j = 0; j < 8; j++) {
            const float p00 = __expf(sacc[j][0] - mn0);
            const float p01 = __expf(sacc[j][1] - mn0);
            const float p10 = __expf(sacc[j][2] - mn1);
            const float p11 = __expf(sacc[j][3] - mn1);
            ps0 += p00 + p01; ps1 += p10 + p11;
            plo[j] = pack_h2(p00, p01);
            phi[j] = pack_h2(p10, p11);
        }
        ps0 += __shfl_xor_sync(0xffffffffu, ps0, 1);
        ps0 += __shfl_xor_sync(0xffffffffu, ps0, 2);
        ps1 += __shfl_xor_sync(0xffffffffu, ps1, 1);
        ps1 += __shfl_xor_sync(0xffffffffu, ps1, 2);
        l0 = l0 * cor0 + ps0;
        l1 = l1 * cor1 + ps1;

        #pragma unroll
        for (int j = 0; j < 16; j++) {
            oacc[j][0] *= cor0; oacc[j][1] *= cor0;
            oacc[j][2] *= cor1; oacc[j][3] *= cor1;
        }

        // O += P @ V : P from registers; warp = 16 rows x 128 d-cols
        #pragma unroll
        for (int kk = 0; kk < 4; kk++) {
            const uint32_t a[4] = { plo[2 * kk], phi[2 * kk],
                                    plo[2 * kk + 1], phi[2 * kk + 1] };
            #pragma unroll
            for (int nt = 0; nt < 8; nt++) {
                uint32_t b[4];
                ldm_x4_t(b, VB + boff + kk * 16 * KS_H * 2 + nt * 32);
                mma_f16(oacc[2 * nt],     a, &b[0]);
                mma_f16(oacc[2 * nt + 1], a, &b[2]);
            }
        }
    }

    // Epilogue: warp-local normalize + fp16 store
    const float i0 = 1.f / l0, i1 = 1.f / l1;
    __half* op0 = out + (size_t)(n * SEQ + row0) * D_MODEL + h * HD;
    __half* op1 = out + (size_t)(n * SEQ + row1) * D_MODEL + h * HD;
    #pragma unroll
    for (int j = 0; j < 16; j++) {
        const int c = j * 8 + 2 * tig;
        *(uint32_t*)&op0[c] = pack_h2(oacc[j][0] * i0, oacc[j][1] * i0);
        *(uint32_t*)&op1[c] = pack_h2(oacc[j][2] * i1, oacc[j][3] * i1);
    }
}

// ---------------------------------------------------------------------------
extern "C" void kernel_launch(void* const* d_in, const int* in_sizes, int n_in,
                              void* d_out, int out_size)
{
    const float* x       = (const float*)d_in[0];
    const float* Wqkv    = (const float*)d_in[1];
    const float* bqkv    = (const float*)d_in[2];
    const float* q_scale = (const float*)d_in[3];
    const float* k_scale = (const float*)d_in[4];
    const float* Wout    = (const float*)d_in[5];
    const float* bout    = (const float*)d_in[6];
    float* out = (float*)d_out;

    __half *qkv, *attn, *xc, *wqT, *woT;
    cudaGetSymbolAddress((void**)&qkv,  g_qkv);
    cudaGetSymbolAddress((void**)&attn, g_attn);
    cudaGetSymbolAddress((void**)&xc,   g_xc);
    cudaGetSymbolAddress((void**)&wqT,  g_wqkvT);
    cudaGetSymbolAddress((void**)&woT,  g_woutT);

    // Prep: fp16 conversion of x; transpose+convert weights
    cvt_x_f16<<<(TOKENS * D_MODEL / 4 + 255) / 256, 256>>>(x, xc, TOKENS * D_MODEL / 4);
    transpose_f16<<<dim3(QKVW / 32, KDIM / 32), 256>>>(Wqkv, wqT, KDIM, QKVW);
    transpose_f16<<<dim3(D_MODEL / 32, KDIM / 32), 256>>>(Wout, woT, KDIM, D_MODEL);

    const int gsmem = GSTG * STG_B;   // 110,592 B
    cudaFuncSetAttribute(gemm_mma<1>, cudaFuncAttributeMaxDynamicSharedMemorySize, gsmem);
    cudaFuncSetAttribute(gemm_mma<0>, cudaFuncAttributeMaxDynamicSharedMemorySize, gsmem);

    // 1) QKV projection + fused RMSNorm (q heads pre-scaled by 1/sqrt(HD))
    gemm_mma<1><<<dim3(QKVW / 128, TOKENS / 128), 256, gsmem>>>(
        xc, wqT, bqkv, qkv, QKVW, KDIM, q_scale, k_scale);

    // 2) FP16 flash attention, P in registers, 1 barrier/tile
    cudaFuncSetAttribute(flash_attn_tc, cudaFuncAttributeMaxDynamicSharedMemorySize, FA_SMEM);
    flash_attn_tc<<<dim3(SEQ / 128, NH, NB), FA_NT, FA_SMEM>>>(qkv, attn);

    // 3) Output projection (fp32 out)
    gemm_mma<0><<<dim3(D_MODEL / 128, TOKENS / 128), 256, gsmem>>>(
        attn, woT, bout, out, D_MODEL, KDIM, nullptr, nullptr);
}